// round 15
// baseline (speedup 1.0000x reference)
#include <cuda_runtime.h>
#include <cuda_fp16.h>
#include <cstdint>
#include <math.h>

// Problem dims (fixed by the dataset)
#define BB 16
#define SS 1024
#define HH 512
#define CC 7
#define MM (BB * SS)        // 16384 rows
#define H3 (3 * HH)         // 1536
#define EPSV 1e-10f
#define MHALF (MM / 2)      // 8192 rows per half

// GEMM tiling
#define BM 128
#define BN 128
#define BK 32
#define LDA 40              // halves, padded (80B rows: cp.async-aligned, ldmatrix conflict-free)
#define LDB 136             // halves, padded (272B rows)
#define NSTG 3
#define STAGE_H (BM * LDA + BK * LDB)              // halves per stage = 9472
#define SMEM_BYTES (NSTG * STAGE_H * 2)            // 56832 B

// ----------------------------------------------------------------------------
// Static scratch (single fp16 planes; no allocations anywhere)
// ----------------------------------------------------------------------------
__device__ __half g_f[4 * MM * HH];                         // text/audio/visual/total
__device__ __half g_G[4 * MM * HH];                         // gating GEMM out (slot 3 = T)
__device__ __half g_h0[MM * H3];                            // gated features
__device__ __half g_sumh[BB * SS * SS];                     // fp16(sp+tp)
__device__ __half g_adj[BB * SS * SS];
__device__ __half g_tmp[MM * HH];                           // feature GEMM out
__device__ __half g_h[MM * HH];                             // layer activations
__device__ __half g_Aw[HH * HH];
__device__ __half g_Wh[HH * HH];
__device__ __half g_W0[H3 * HH];
__device__ __half g_W1[HH * HH];
__device__ __half g_W2[HH * HH];
__device__ float g_ent[3 * MM];
__device__ float g_dsi[BB * SS];
__device__ float g_wlast[HH];
__device__ float g_WcT[CC * HH];

// ----------------------------------------------------------------------------
// Helpers
// ----------------------------------------------------------------------------
__device__ __forceinline__ unsigned s2u(const void* p) {
    return (unsigned)__cvta_generic_to_shared(p);
}

__device__ __forceinline__ void store4h(float4 v, __half* p, long long idx) {
    *(__half2*)(p + idx)     = __halves2half2(__float2half_rn(v.x), __float2half_rn(v.y));
    *(__half2*)(p + idx + 2) = __halves2half2(__float2half_rn(v.z), __float2half_rn(v.w));
}

#define MMA16816(d, a, b)                                                  \
    asm volatile(                                                          \
        "mma.sync.aligned.m16n8k16.row.col.f32.f16.f16.f32 "               \
        "{%0,%1,%2,%3}, {%4,%5,%6,%7}, {%8,%9}, {%0,%1,%2,%3};\n"          \
        : "+f"(d[0]), "+f"(d[1]), "+f"(d[2]), "+f"(d[3])                   \
        : "r"(a[0]), "r"(a[1]), "r"(a[2]), "r"(a[3]), "r"(b[0]), "r"(b[1]))

#define LDSM_X4(r0, r1, r2, r3, addr)                                      \
    asm volatile("ldmatrix.sync.aligned.m8n8.x4.shared.b16 "               \
                 "{%0,%1,%2,%3}, [%4];\n"                                  \
                 : "=r"(r0), "=r"(r1), "=r"(r2), "=r"(r3) : "r"(addr))

#define LDSM_X4T(r0, r1, r2, r3, addr)                                     \
    asm volatile("ldmatrix.sync.aligned.m8n8.x4.trans.shared.b16 "         \
                 "{%0,%1,%2,%3}, [%4];\n"                                  \
                 : "=r"(r0), "=r"(r1), "=r"(r2), "=r"(r3) : "r"(addr))

#define CP16(dst, src)                                                     \
    asm volatile("cp.async.cg.shared.global [%0], [%1], 16;\n"             \
                 :: "r"(dst), "l"(src))
#define CP_COMMIT asm volatile("cp.async.commit_group;\n" ::: "memory")
#define CP_WAIT(n) asm volatile("cp.async.wait_group %0;\n" :: "n"(n) : "memory")

// ----------------------------------------------------------------------------
// fp16 tensor-core GEMM, 3-stage cp.async pipeline, 1 MMA per logical tile.
// C = A[M,K] @ B[K,N].  EPI: 0 = none, 1 = bias+relu.
// SELB: 0 = B0g (+z*sB), 1 = gating mode: B = (z < 3) ? B0g : B1g, sB ignored.
// ----------------------------------------------------------------------------
template <int EPI, int SELB>
__global__ void __launch_bounds__(256, 2) mma_gemm(
    const __half* __restrict__ A0g, const __half* __restrict__ B0g,
    const __half* __restrict__ B1g,
    const float* __restrict__ bias, __half* __restrict__ Chg,
    int M, int N, int K, long long sA, long long sB, long long sC)
{
    extern __shared__ __half sm[];
    const __half* A0 = A0g + (long long)blockIdx.z * sA;
    const __half* B0 = SELB ? ((blockIdx.z < 3) ? B0g : B1g)
                            : (B0g + (long long)blockIdx.z * sB);
    __half* Ch = Chg + (long long)blockIdx.z * sC;

    int t = threadIdx.x, lane = t & 31, wid = t >> 5;
    int warp_m = wid >> 2, warp_n = wid & 3;
    int brow = blockIdx.y * BM, bcol = blockIdx.x * BN;
    int KT = K / BK;

    float acc[4][4][4];
    #pragma unroll
    for (int i = 0; i < 4; i++)
        #pragma unroll
        for (int j = 0; j < 4; j++)
            #pragma unroll
            for (int q = 0; q < 4; q++) acc[i][j][q] = 0.0f;

    auto load_tile = [&](int kt, int s) {
        int k0 = kt * BK;
        __half* st = sm + s * STAGE_H;
        #pragma unroll
        for (int i = 0; i < 2; i++) {
            int q = t + i * 256;
            int ra = q >> 2, ca = (q & 3) << 3;
            long long asrc = (long long)(brow + ra) * K + k0 + ca;
            CP16(s2u(st + ra * LDA + ca), A0 + asrc);
            int rb = q >> 4, cb = (q & 15) << 3;
            long long bsrc = (long long)(k0 + rb) * N + bcol + cb;
            CP16(s2u(st + BM * LDA + rb * LDB + cb), B0 + bsrc);
        }
    };

    load_tile(0, 0); CP_COMMIT;
    load_tile(1, 1); CP_COMMIT;

    int s = 0;
    for (int kt = 0; kt < KT; kt++) {
        if (kt + 2 < KT) { CP_WAIT(1); } else { CP_WAIT(0); }
        __syncthreads();

        if (kt + 2 < KT) { load_tile(kt + 2, (s + 2) % NSTG); CP_COMMIT; }

        const __half* cA0 = sm + s * STAGE_H;
        const __half* cB0 = cA0 + BM * LDA;

        #pragma unroll
        for (int kk = 0; kk < BK; kk += 16) {
            unsigned a0[4][4], b0[4][2];
            int arow = warp_m * 64 + (lane & 15);
            int acol = kk + ((lane >> 4) << 3);
            #pragma unroll
            for (int tm = 0; tm < 4; tm++)
                LDSM_X4(a0[tm][0], a0[tm][1], a0[tm][2], a0[tm][3],
                        s2u(&cA0[(arow + tm * 16) * LDA + acol]));
            int brow_ = kk + (lane & 15);
            #pragma unroll
            for (int tp = 0; tp < 2; tp++) {
                int bc = warp_n * 32 + tp * 16 + ((lane >> 4) << 3);
                LDSM_X4T(b0[2 * tp][0], b0[2 * tp][1],
                         b0[2 * tp + 1][0], b0[2 * tp + 1][1],
                         s2u(&cB0[brow_ * LDB + bc]));
            }
            #pragma unroll
            for (int tm = 0; tm < 4; tm++)
                #pragma unroll
                for (int tn = 0; tn < 4; tn++)
                    MMA16816(acc[tm][tn], a0[tm], b0[tn]);
        }
        s = (s + 1) % NSTG;
    }

    int g = lane >> 2, tig = lane & 3;
    #pragma unroll
    for (int tm = 0; tm < 4; tm++)
        #pragma unroll
        for (int tn = 0; tn < 4; tn++) {
            int row = brow + warp_m * 64 + tm * 16 + g;
            int col = bcol + warp_n * 32 + tn * 8 + tig * 2;
            float2 v0 = make_float2(acc[tm][tn][0], acc[tm][tn][1]);
            float2 v1 = make_float2(acc[tm][tn][2], acc[tm][tn][3]);
            if (EPI == 1) {
                float b0v = bias[col], b1v = bias[col + 1];
                v0.x = fmaxf(v0.x + b0v, 0.0f); v0.y = fmaxf(v0.y + b1v, 0.0f);
                v1.x = fmaxf(v1.x + b0v, 0.0f); v1.y = fmaxf(v1.y + b1v, 0.0f);
            }
            long long idx0 = (long long)row * N + col;
            long long idx1 = (long long)(row + 8) * N + col;
            *(__half2*)(Ch + idx0) = __halves2half2(__float2half_rn(v0.x), __float2half_rn(v0.y));
            *(__half2*)(Ch + idx1) = __halves2half2(__float2half_rn(v1.x), __float2half_rn(v1.y));
        }
}

// ----------------------------------------------------------------------------
// Fused: entropy + fp16 convert of feats + total (slot 3) — half rows
// ----------------------------------------------------------------------------
__global__ void prep_feats(const float* __restrict__ text,
                           const float* __restrict__ audio,
                           const float* __restrict__ visual, int rbase) {
    __shared__ float sh[3][4];
    long long r = rbase + blockIdx.x;
    int tid = threadIdx.x, lane = tid & 31, w = tid >> 5;
    long long off = r * HH + tid * 4;
    float4 v0 = *(const float4*)(text + off);
    float4 v1 = *(const float4*)(audio + off);
    float4 v2 = *(const float4*)(visual + off);

    float a0x = fabsf(v0.x), a0y = fabsf(v0.y), a0z = fabsf(v0.z), a0w = fabsf(v0.w);
    float a1x = fabsf(v1.x), a1y = fabsf(v1.y), a1z = fabsf(v1.z), a1w = fabsf(v1.w);
    float a2x = fabsf(v2.x), a2y = fabsf(v2.y), a2z = fabsf(v2.z), a2w = fabsf(v2.w);
    float s0 = a0x + a0y + a0z + a0w;
    float s1 = a1x + a1y + a1z + a1w;
    float s2 = a2x + a2y + a2z + a2w;
    #pragma unroll
    for (int o = 16; o; o >>= 1) {
        s0 += __shfl_down_sync(0xffffffffu, s0, o);
        s1 += __shfl_down_sync(0xffffffffu, s1, o);
        s2 += __shfl_down_sync(0xffffffffu, s2, o);
    }
    if (lane == 0) { sh[0][w] = s0; sh[1][w] = s1; sh[2][w] = s2; }
    __syncthreads();
    float t0 = sh[0][0] + sh[0][1] + sh[0][2] + sh[0][3];
    float t1 = sh[1][0] + sh[1][1] + sh[1][2] + sh[1][3];
    float t2 = sh[2][0] + sh[2][1] + sh[2][2] + sh[2][3];
    float i0 = 1.0f / (t0 + EPSV), i1 = 1.0f / (t1 + EPSV), i2 = 1.0f / (t2 + EPSV);

    float e0, e1, e2;
    {
        float f0 = a0x * i0, f1 = a0y * i0, f2 = a0z * i0, f3 = a0w * i0;
        e0 = f0 * logf(f0 + EPSV) + f1 * logf(f1 + EPSV)
           + f2 * logf(f2 + EPSV) + f3 * logf(f3 + EPSV);
    }
    {
        float f0 = a1x * i1, f1 = a1y * i1, f2 = a1z * i1, f3 = a1w * i1;
        e1 = f0 * logf(f0 + EPSV) + f1 * logf(f1 + EPSV)
           + f2 * logf(f2 + EPSV) + f3 * logf(f3 + EPSV);
    }
    {
        float f0 = a2x * i2, f1 = a2y * i2, f2 = a2z * i2, f3 = a2w * i2;
        e2 = f0 * logf(f0 + EPSV) + f1 * logf(f1 + EPSV)
           + f2 * logf(f2 + EPSV) + f3 * logf(f3 + EPSV);
    }
    #pragma unroll
    for (int o = 16; o; o >>= 1) {
        e0 += __shfl_down_sync(0xffffffffu, e0, o);
        e1 += __shfl_down_sync(0xffffffffu, e1, o);
        e2 += __shfl_down_sync(0xffffffffu, e2, o);
    }
    __syncthreads();
    if (lane == 0) { sh[0][w] = e0; sh[1][w] = e1; sh[2][w] = e2; }
    __syncthreads();
    if (tid == 0) {
        g_ent[0 * MM + r] = -(sh[0][0] + sh[0][1] + sh[0][2] + sh[0][3]);
        g_ent[1 * MM + r] = -(sh[1][0] + sh[1][1] + sh[1][2] + sh[1][3]);
        g_ent[2 * MM + r] = -(sh[2][0] + sh[2][1] + sh[2][2] + sh[2][3]);
    }

    store4h(v0, g_f, 0LL * MM * HH + off);
    store4h(v1, g_f, 1LL * MM * HH + off);
    store4h(v2, g_f, 2LL * MM * HH + off);
    float4 tq = make_float4(v0.x + v1.x + v2.x, v0.y + v1.y + v2.y,
                            v0.z + v1.z + v2.z, v0.w + v1.w + v2.w);
    store4h(tq, g_f, 3LL * MM * HH + off);
}

// ----------------------------------------------------------------------------
// Weight prep (merged: gate weights + Wc transpose)
// ----------------------------------------------------------------------------
__global__ void prep_weights(const float* __restrict__ gW, const float* __restrict__ Wc) {
    int idx = blockIdx.x * blockDim.x + threadIdx.x;
    if (idx < HH * HH) {
        float wa = gW[idx];
        float wb = gW[HH * HH + idx];
        float wc = gW[2 * HH * HH + idx];
        g_Aw[idx] = __float2half_rn(wa + wb - 0.5f * wc);
        g_Wh[idx] = __float2half_rn(0.5f * wc);
    }
    if (idx < HH) g_wlast[idx] = gW[3 * HH * HH + idx];
    if (idx < HH * CC) {
        int k = idx / CC, c = idx % CC;
        g_WcT[c * HH + k] = Wc[k * CC + c];
    }
}

// All three GNN weight conversions in one launch
#define N4_W0 (H3 * HH / 4)
#define N4_W1 (HH * HH / 4)
__global__ void conv_w_all(const float* __restrict__ W0, const float* __restrict__ W1,
                           const float* __restrict__ W2) {
    int i = blockIdx.x * blockDim.x + threadIdx.x;
    if (i < N4_W0) {
        float4 v = ((const float4*)W0)[i];
        store4h(v, g_W0, (long long)i * 4);
    } else if (i < N4_W0 + N4_W1) {
        int j = i - N4_W0;
        float4 v = ((const float4*)W1)[j];
        store4h(v, g_W1, (long long)j * 4);
    } else if (i < N4_W0 + 2 * N4_W1) {
        int j = i - N4_W0 - N4_W1;
        float4 v = ((const float4*)W2)[j];
        store4h(v, g_W2, (long long)j * 4);
    }
}

// ----------------------------------------------------------------------------
// gate_fuse (half): rows [rbase, rbase+MHALF)
// ----------------------------------------------------------------------------
__global__ void gate_fuse_kernel(const float* __restrict__ gate_b, int rbase) {
    long long r = rbase + blockIdx.x;
    int m = blockIdx.y;
    float e = g_ent[(long long)m * MM + r];
    int j = threadIdx.x * 4;
    long long gi = ((long long)m * MM + r) * HH + j;
    long long ti = (3LL * MM + r) * HH + j;
    float2 gv0 = __half22float2(*(const __half2*)(g_G + gi));
    float2 gv1 = __half22float2(*(const __half2*)(g_G + gi + 2));
    float2 tv0 = __half22float2(*(const __half2*)(g_G + ti));
    float2 tv1 = __half22float2(*(const __half2*)(g_G + ti + 2));
    float2 fv0 = __half22float2(*(const __half2*)(g_f + gi));
    float2 fv1 = __half22float2(*(const __half2*)(g_f + gi + 2));
    float4 wv = *(const float4*)(g_wlast + j);
    float4 bv = *(const float4*)(gate_b + j);

    float zx = gv0.x + tv0.x + e * wv.x + bv.x;
    float zy = gv0.y + tv0.y + e * wv.y + bv.y;
    float zz = gv1.x + tv1.x + e * wv.z + bv.z;
    float zw = gv1.y + tv1.y + e * wv.w + bv.w;
    float4 o;
    o.x = fv0.x / (1.0f + expf(-zx));
    o.y = fv0.y / (1.0f + expf(-zy));
    o.z = fv1.x / (1.0f + expf(-zz));
    o.w = fv1.y / (1.0f + expf(-zw));
    store4h(o, g_h0, r * H3 + m * HH + j);
}

// ----------------------------------------------------------------------------
// Degree: dsi + cache fp16(sp+tp)
// ----------------------------------------------------------------------------
__global__ void degree_kernel(const float* __restrict__ sp, const float* __restrict__ tp) {
    __shared__ float sh[8];
    long long b = blockIdx.y, i = blockIdx.x;
    long long base = (b * SS + i) * SS;
    const float4* rs = (const float4*)(sp + base);
    const float4* rt = (const float4*)(tp + base);
    float4 a = rs[threadIdx.x], c = rt[threadIdx.x];
    float4 sm4 = make_float4(a.x + c.x, a.y + c.y, a.z + c.z, a.w + c.w);
    store4h(sm4, g_sumh, base + threadIdx.x * 4);
    float s = sm4.x + sm4.y + sm4.z + sm4.w;
    #pragma unroll
    for (int o = 16; o; o >>= 1) s += __shfl_down_sync(0xffffffffu, s, o);
    int lane = threadIdx.x & 31, w = threadIdx.x >> 5;
    if (lane == 0) sh[w] = s;
    __syncthreads();
    if (threadIdx.x == 0) {
        float D = 1.0f + 0.5f * (sh[0] + sh[1] + sh[2] + sh[3] + sh[4] + sh[5] + sh[6] + sh[7]);
        g_dsi[b * SS + i] = 1.0f / sqrtf(D + EPSV);
    }
}

__global__ void normadj_kernel() {
    long long n4 = (long long)BB * SS * SS / 4;
    for (long long g = (long long)blockIdx.x * blockDim.x + threadIdx.x; g < n4;
         g += (long long)gridDim.x * blockDim.x) {
        long long e = g * 4;
        int b = (int)(e / ((long long)SS * SS));
        long long rrem = e % ((long long)SS * SS);
        int i = (int)(rrem / SS);
        int j = (int)(rrem % SS);
        float2 s0 = __half22float2(*(const __half2*)(g_sumh + e));
        float2 s1 = __half22float2(*(const __half2*)(g_sumh + e + 2));
        float di = g_dsi[(long long)b * SS + i];
        const float* dj = g_dsi + (long long)b * SS + j;
        float4 o;
        o.x = (0.5f * s0.x + (j + 0 == i ? 1.0f : 0.0f)) * di * dj[0];
        o.y = (0.5f * s0.y + (j + 1 == i ? 1.0f : 0.0f)) * di * dj[1];
        o.z = (0.5f * s1.x + (j + 2 == i ? 1.0f : 0.0f)) * di * dj[2];
        o.w = (0.5f * s1.y + (j + 3 == i ? 1.0f : 0.0f)) * di * dj[3];
        store4h(o, g_adj, e);
    }
}

// ----------------------------------------------------------------------------
// Classifier (half): rows [rbase, rbase+MHALF)
// ----------------------------------------------------------------------------
__global__ void classifier_kernel(const float* __restrict__ bc, float* __restrict__ out,
                                  int rbase) {
    __shared__ float sh[HH];
    long long r = rbase + blockIdx.x;
    for (int k = threadIdx.x; k < HH; k += 224)
        sh[k] = __half2float(g_h[r * HH + k]);
    __syncthreads();
    int w = threadIdx.x >> 5, lane = threadIdx.x & 31;
    if (w < CC) {
        const float* wrow = g_WcT + w * HH;
        float s = 0.0f;
        #pragma unroll
        for (int k = lane; k < HH; k += 32) s += sh[k] * wrow[k];
        #pragma unroll
        for (int o = 16; o; o >>= 1) s += __shfl_down_sync(0xffffffffu, s, o);
        if (lane == 0) out[r * CC + w] = s + bc[w];
    }
}

// ----------------------------------------------------------------------------
// Launch — per-half pipelines: main = half-A (feats→gate→fuse→GNN→class),
// s2 = prep + half-B chain, s3 = feats-B. No full-width barriers.
// ----------------------------------------------------------------------------
extern "C" void kernel_launch(void* const* d_in, const int* in_sizes, int n_in,
                              void* d_out, int out_size) {
    const float* text   = (const float*)d_in[0];
    const float* audio  = (const float*)d_in[1];
    const float* visual = (const float*)d_in[2];
    const float* sp     = (const float*)d_in[3];
    const float* tp     = (const float*)d_in[4];
    const float* gate_W = (const float*)d_in[6];
    const float* gate_b = (const float*)d_in[7];
    const float* W0 = (const float*)d_in[8];
    const float* b0 = (const float*)d_in[9];
    const float* W1 = (const float*)d_in[10];
    const float* b1 = (const float*)d_in[11];
    const float* W2 = (const float*)d_in[12];
    const float* b2 = (const float*)d_in[13];
    const float* Wc = (const float*)d_in[14];
    const float* bc = (const float*)d_in[15];
    float* out = (float*)d_out;

    static bool init_done = false;
    static cudaStream_t s2, s3;
    static cudaEvent_t eFork, ePW, eJoin, eFB, eB;
    if (!init_done) {
        cudaFuncSetAttribute(mma_gemm<0, 0>, cudaFuncAttributeMaxDynamicSharedMemorySize, SMEM_BYTES);
        cudaFuncSetAttribute(mma_gemm<1, 0>, cudaFuncAttributeMaxDynamicSharedMemorySize, SMEM_BYTES);
        cudaFuncSetAttribute(mma_gemm<0, 1>, cudaFuncAttributeMaxDynamicSharedMemorySize, SMEM_BYTES);
        cudaStreamCreateWithFlags(&s2, cudaStreamNonBlocking);
        cudaStreamCreateWithFlags(&s3, cudaStreamNonBlocking);
        cudaEventCreateWithFlags(&eFork, cudaEventDisableTiming);
        cudaEventCreateWithFlags(&ePW, cudaEventDisableTiming);
        cudaEventCreateWithFlags(&eJoin, cudaEventDisableTiming);
        cudaEventCreateWithFlags(&eFB, cudaEventDisableTiming);
        cudaEventCreateWithFlags(&eB, cudaEventDisableTiming);
        init_done = true;
    }

    #define SYM(p, s) cudaGetSymbolAddress((void**)&p, s)
    __half *f, *G, *h0, *adj, *tmp, *h;
    __half *Aw, *Wh, *W0p, *W1p, *W2p;
    SYM(f, g_f); SYM(G, g_G);
    SYM(h0, g_h0); SYM(adj, g_adj);
    SYM(tmp, g_tmp); SYM(h, g_h);
    SYM(Aw, g_Aw); SYM(Wh, g_Wh);
    SYM(W0p, g_W0); SYM(W1p, g_W1); SYM(W2p, g_W2);
    #undef SYM

    long long sF = (long long)MM * HH;
    dim3 gateh_grid(HH / BN, MHALF / BM, 4);       // (4, 64, 4) per half
    dim3 half_grid(HH / BN, MHALF / BM, 1);        // (4, 64, 1)
    dim3 adjh_grid(HH / BN, SS / BM, BB / 2);      // (4, 8, 8)
    long long sAdj = (long long)SS * SS, sL = (long long)SS * HH;

    // half-B pointer offsets (rows/batches 8192.. / 8..15)
    const long long hRow  = (long long)MHALF * HH;    // feats/G/tmp/h rows
    const long long hOffF = (long long)MHALF * H3;    // h0 rows
    const long long hOffA = 8LL * sAdj;               // adj batches

    // fork
    cudaEventRecord(eFork, 0);
    cudaStreamWaitEvent(s2, eFork, 0);
    cudaStreamWaitEvent(s3, eFork, 0);

    // s3: feats for half B
    prep_feats<<<MHALF, 128, 0, s3>>>(text, audio, visual, MHALF);
    cudaEventRecord(eFB, s3);

    // s2: weights + adjacency prep
    prep_weights<<<(HH * HH + 255) / 256, 256, 0, s2>>>(gate_W, Wc);
    cudaEventRecord(ePW, s2);
    degree_kernel<<<dim3(SS, BB), 256, 0, s2>>>(sp, tp);
    normadj_kernel<<<8192, 256, 0, s2>>>();
    conv_w_all<<<(N4_W0 + 2 * N4_W1 + 255) / 256, 256, 0, s2>>>(W0, W1, W2);
    cudaEventRecord(eJoin, s2);

    // main: feats-A -> gate-A -> fuse-A
    prep_feats<<<MHALF, 128>>>(text, audio, visual, 0);
    cudaStreamWaitEvent(0, ePW, 0);
    mma_gemm<0, 1><<<gateh_grid, 256, SMEM_BYTES>>>(f, Aw, Wh, nullptr, G,
                                                    MHALF, HH, HH, sF, 0, sF);
    gate_fuse_kernel<<<dim3(MHALF, 3), 128>>>(gate_b, 0);

    // s2: gate-B -> fuse-B (needs feats-B + weights; ePW implicit via s2 order)
    cudaStreamWaitEvent(s2, eFB, 0);
    mma_gemm<0, 1><<<gateh_grid, 256, SMEM_BYTES, s2>>>(f + hRow, Aw, Wh, nullptr, G + hRow,
                                                        MHALF, HH, HH, sF, 0, sF);
    gate_fuse_kernel<<<dim3(MHALF, 3), 128, 0, s2>>>(gate_b, MHALF);

    // main needs adjacency prep before its GNN chain
    cudaStreamWaitEvent(0, eJoin, 0);

    // Layer 0
    mma_gemm<0, 0><<<half_grid, 256, SMEM_BYTES>>>(h0, W0p, nullptr, nullptr, tmp,
                                                   MHALF, HH, H3, 0, 0, 0);
    mma_gemm<0, 0><<<half_grid, 256, SMEM_BYTES, s2>>>(h0 + hOffF, W0p, nullptr, nullptr,
                                                       tmp + hRow, MHALF, HH, H3, 0, 0, 0);
    mma_gemm<1, 0><<<adjh_grid, 256, SMEM_BYTES>>>(adj, tmp, nullptr, b0, h,
                                                   SS, HH, SS, sAdj, sL, sL);
    mma_gemm<1, 0><<<adjh_grid, 256, SMEM_BYTES, s2>>>(adj + hOffA, tmp + hRow, nullptr, b0,
                                                       h + hRow, SS, HH, SS, sAdj, sL, sL);
    // Layer 1
    mma_gemm<0, 0><<<half_grid, 256, SMEM_BYTES>>>(h, W1p, nullptr, nullptr, tmp,
                                                   MHALF, HH, HH, 0, 0, 0);
    mma_gemm<0, 0><<<half_grid, 256, SMEM_BYTES, s2>>>(h + hRow, W1p, nullptr, nullptr,
                                                       tmp + hRow, MHALF, HH, HH, 0, 0, 0);
    mma_gemm<1, 0><<<adjh_grid, 256, SMEM_BYTES>>>(adj, tmp, nullptr, b1, h,
                                                   SS, HH, SS, sAdj, sL, sL);
    mma_gemm<1, 0><<<adjh_grid, 256, SMEM_BYTES, s2>>>(adj + hOffA, tmp + hRow, nullptr, b1,
                                                       h + hRow, SS, HH, SS, sAdj, sL, sL);
    // Layer 2
    mma_gemm<0, 0><<<half_grid, 256, SMEM_BYTES>>>(h, W2p, nullptr, nullptr, tmp,
                                                   MHALF, HH, HH, 0, 0, 0);
    mma_gemm<0, 0><<<half_grid, 256, SMEM_BYTES, s2>>>(h + hRow, W2p, nullptr, nullptr,
                                                       tmp + hRow, MHALF, HH, HH, 0, 0, 0);
    mma_gemm<1, 0><<<adjh_grid, 256, SMEM_BYTES>>>(adj, tmp, nullptr, b2, h,
                                                   SS, HH, SS, sAdj, sL, sL);
    mma_gemm<1, 0><<<adjh_grid, 256, SMEM_BYTES, s2>>>(adj + hOffA, tmp + hRow, nullptr, b2,
                                                       h + hRow, SS, HH, SS, sAdj, sL, sL);

    // classifier per half, join at end
    classifier_kernel<<<MHALF, 224>>>(bc, out, 0);
    classifier_kernel<<<MHALF, 224, 0, s2>>>(bc, out, MHALF);
    cudaEventRecord(eB, s2);
    cudaStreamWaitEvent(0, eB, 0);
}

// round 16
// speedup vs baseline: 1.0266x; 1.0266x over previous
#include <cuda_runtime.h>
#include <cuda_fp16.h>
#include <cstdint>
#include <math.h>

// Problem dims (fixed by the dataset)
#define BB 16
#define SS 1024
#define HH 512
#define CC 7
#define MM (BB * SS)        // 16384 rows
#define H3 (3 * HH)         // 1536
#define EPSV 1e-10f
#define MHALF (MM / 2)      // 8192 rows per half

// GEMM tiling
#define BM 128
#define BN 128
#define BK 32
#define LDA 40              // halves, padded (80B rows: cp.async-aligned, ldmatrix conflict-free)
#define LDB 136             // halves, padded (272B rows)
#define NSTG 3
#define STAGE_H (BM * LDA + BK * LDB)              // halves per stage = 9472
#define SMEM_BYTES (NSTG * STAGE_H * 2)            // 56832 B

// ----------------------------------------------------------------------------
// Static scratch (single fp16 planes; no allocations anywhere)
// ----------------------------------------------------------------------------
__device__ __half g_f[4 * MM * HH];                         // text/audio/visual/total
__device__ __half g_G[4 * MM * HH];                         // gating GEMM out (slot 3 = T)
__device__ __half g_h0[MM * H3];                            // gated features
__device__ __half g_sumh[BB * SS * SS];                     // fp16(sp+tp)
__device__ __half g_adj[BB * SS * SS];
__device__ __half g_tmp[MM * HH];                           // feature GEMM out
__device__ __half g_h[MM * HH];                             // layer activations
__device__ __half g_Aw[HH * HH];
__device__ __half g_Wh[HH * HH];
__device__ __half g_W0[H3 * HH];
__device__ __half g_W1[HH * HH];
__device__ __half g_W2[HH * HH];
__device__ float g_ent[3 * MM];
__device__ float g_dsi[BB * SS];
__device__ float g_wlast[HH];
__device__ float g_WcT[CC * HH];

// ----------------------------------------------------------------------------
// Helpers
// ----------------------------------------------------------------------------
__device__ __forceinline__ unsigned s2u(const void* p) {
    return (unsigned)__cvta_generic_to_shared(p);
}

__device__ __forceinline__ void store4h(float4 v, __half* p, long long idx) {
    *(__half2*)(p + idx)     = __halves2half2(__float2half_rn(v.x), __float2half_rn(v.y));
    *(__half2*)(p + idx + 2) = __halves2half2(__float2half_rn(v.z), __float2half_rn(v.w));
}

#define MMA16816(d, a, b)                                                  \
    asm volatile(                                                          \
        "mma.sync.aligned.m16n8k16.row.col.f32.f16.f16.f32 "               \
        "{%0,%1,%2,%3}, {%4,%5,%6,%7}, {%8,%9}, {%0,%1,%2,%3};\n"          \
        : "+f"(d[0]), "+f"(d[1]), "+f"(d[2]), "+f"(d[3])                   \
        : "r"(a[0]), "r"(a[1]), "r"(a[2]), "r"(a[3]), "r"(b[0]), "r"(b[1]))

#define LDSM_X4(r0, r1, r2, r3, addr)                                      \
    asm volatile("ldmatrix.sync.aligned.m8n8.x4.shared.b16 "               \
                 "{%0,%1,%2,%3}, [%4];\n"                                  \
                 : "=r"(r0), "=r"(r1), "=r"(r2), "=r"(r3) : "r"(addr))

#define LDSM_X4T(r0, r1, r2, r3, addr)                                     \
    asm volatile("ldmatrix.sync.aligned.m8n8.x4.trans.shared.b16 "         \
                 "{%0,%1,%2,%3}, [%4];\n"                                  \
                 : "=r"(r0), "=r"(r1), "=r"(r2), "=r"(r3) : "r"(addr))

#define CP16(dst, src)                                                     \
    asm volatile("cp.async.cg.shared.global [%0], [%1], 16;\n"             \
                 :: "r"(dst), "l"(src))
#define CP_COMMIT asm volatile("cp.async.commit_group;\n" ::: "memory")
#define CP_WAIT(n) asm volatile("cp.async.wait_group %0;\n" :: "n"(n) : "memory")

// ----------------------------------------------------------------------------
// fp16 tensor-core GEMM, 3-stage cp.async pipeline, 1 MMA per logical tile.
// C = A[M,K] @ B[K,N].  EPI: 0 = none, 1 = bias+relu.
// SELB: 0 = B0g (+z*sB), 1 = gating mode: B = (z < 3) ? B0g : B1g, sB ignored.
// ----------------------------------------------------------------------------
template <int EPI, int SELB>
__global__ void __launch_bounds__(256, 2) mma_gemm(
    const __half* __restrict__ A0g, const __half* __restrict__ B0g,
    const __half* __restrict__ B1g,
    const float* __restrict__ bias, __half* __restrict__ Chg,
    int M, int N, int K, long long sA, long long sB, long long sC)
{
    extern __shared__ __half sm[];
    const __half* A0 = A0g + (long long)blockIdx.z * sA;
    const __half* B0 = SELB ? ((blockIdx.z < 3) ? B0g : B1g)
                            : (B0g + (long long)blockIdx.z * sB);
    __half* Ch = Chg + (long long)blockIdx.z * sC;

    int t = threadIdx.x, lane = t & 31, wid = t >> 5;
    int warp_m = wid >> 2, warp_n = wid & 3;
    int brow = blockIdx.y * BM, bcol = blockIdx.x * BN;
    int KT = K / BK;

    float acc[4][4][4];
    #pragma unroll
    for (int i = 0; i < 4; i++)
        #pragma unroll
        for (int j = 0; j < 4; j++)
            #pragma unroll
            for (int q = 0; q < 4; q++) acc[i][j][q] = 0.0f;

    auto load_tile = [&](int kt, int s) {
        int k0 = kt * BK;
        __half* st = sm + s * STAGE_H;
        #pragma unroll
        for (int i = 0; i < 2; i++) {
            int q = t + i * 256;
            int ra = q >> 2, ca = (q & 3) << 3;
            long long asrc = (long long)(brow + ra) * K + k0 + ca;
            CP16(s2u(st + ra * LDA + ca), A0 + asrc);
            int rb = q >> 4, cb = (q & 15) << 3;
            long long bsrc = (long long)(k0 + rb) * N + bcol + cb;
            CP16(s2u(st + BM * LDA + rb * LDB + cb), B0 + bsrc);
        }
    };

    load_tile(0, 0); CP_COMMIT;
    load_tile(1, 1); CP_COMMIT;

    int s = 0;
    for (int kt = 0; kt < KT; kt++) {
        if (kt + 2 < KT) { CP_WAIT(1); } else { CP_WAIT(0); }
        __syncthreads();

        if (kt + 2 < KT) { load_tile(kt + 2, (s + 2) % NSTG); CP_COMMIT; }

        const __half* cA0 = sm + s * STAGE_H;
        const __half* cB0 = cA0 + BM * LDA;

        #pragma unroll
        for (int kk = 0; kk < BK; kk += 16) {
            unsigned a0[4][4], b0[4][2];
            int arow = warp_m * 64 + (lane & 15);
            int acol = kk + ((lane >> 4) << 3);
            #pragma unroll
            for (int tm = 0; tm < 4; tm++)
                LDSM_X4(a0[tm][0], a0[tm][1], a0[tm][2], a0[tm][3],
                        s2u(&cA0[(arow + tm * 16) * LDA + acol]));
            int brow_ = kk + (lane & 15);
            #pragma unroll
            for (int tp = 0; tp < 2; tp++) {
                int bc = warp_n * 32 + tp * 16 + ((lane >> 4) << 3);
                LDSM_X4T(b0[2 * tp][0], b0[2 * tp][1],
                         b0[2 * tp + 1][0], b0[2 * tp + 1][1],
                         s2u(&cB0[brow_ * LDB + bc]));
            }
            #pragma unroll
            for (int tm = 0; tm < 4; tm++)
                #pragma unroll
                for (int tn = 0; tn < 4; tn++)
                    MMA16816(acc[tm][tn], a0[tm], b0[tn]);
        }
        s = (s + 1) % NSTG;
    }

    int g = lane >> 2, tig = lane & 3;
    #pragma unroll
    for (int tm = 0; tm < 4; tm++)
        #pragma unroll
        for (int tn = 0; tn < 4; tn++) {
            int row = brow + warp_m * 64 + tm * 16 + g;
            int col = bcol + warp_n * 32 + tn * 8 + tig * 2;
            float2 v0 = make_float2(acc[tm][tn][0], acc[tm][tn][1]);
            float2 v1 = make_float2(acc[tm][tn][2], acc[tm][tn][3]);
            if (EPI == 1) {
                float b0v = bias[col], b1v = bias[col + 1];
                v0.x = fmaxf(v0.x + b0v, 0.0f); v0.y = fmaxf(v0.y + b1v, 0.0f);
                v1.x = fmaxf(v1.x + b0v, 0.0f); v1.y = fmaxf(v1.y + b1v, 0.0f);
            }
            long long idx0 = (long long)row * N + col;
            long long idx1 = (long long)(row + 8) * N + col;
            *(__half2*)(Ch + idx0) = __halves2half2(__float2half_rn(v0.x), __float2half_rn(v0.y));
            *(__half2*)(Ch + idx1) = __halves2half2(__float2half_rn(v1.x), __float2half_rn(v1.y));
        }
}

// ----------------------------------------------------------------------------
// Fused: entropy + fp16 convert of feats + total (slot 3) — half rows
// ----------------------------------------------------------------------------
__global__ void prep_feats(const float* __restrict__ text,
                           const float* __restrict__ audio,
                           const float* __restrict__ visual, int rbase) {
    __shared__ float sh[3][4];
    long long r = rbase + blockIdx.x;
    int tid = threadIdx.x, lane = tid & 31, w = tid >> 5;
    long long off = r * HH + tid * 4;
    float4 v0 = *(const float4*)(text + off);
    float4 v1 = *(const float4*)(audio + off);
    float4 v2 = *(const float4*)(visual + off);

    float a0x = fabsf(v0.x), a0y = fabsf(v0.y), a0z = fabsf(v0.z), a0w = fabsf(v0.w);
    float a1x = fabsf(v1.x), a1y = fabsf(v1.y), a1z = fabsf(v1.z), a1w = fabsf(v1.w);
    float a2x = fabsf(v2.x), a2y = fabsf(v2.y), a2z = fabsf(v2.z), a2w = fabsf(v2.w);
    float s0 = a0x + a0y + a0z + a0w;
    float s1 = a1x + a1y + a1z + a1w;
    float s2 = a2x + a2y + a2z + a2w;
    #pragma unroll
    for (int o = 16; o; o >>= 1) {
        s0 += __shfl_down_sync(0xffffffffu, s0, o);
        s1 += __shfl_down_sync(0xffffffffu, s1, o);
        s2 += __shfl_down_sync(0xffffffffu, s2, o);
    }
    if (lane == 0) { sh[0][w] = s0; sh[1][w] = s1; sh[2][w] = s2; }
    __syncthreads();
    float t0 = sh[0][0] + sh[0][1] + sh[0][2] + sh[0][3];
    float t1 = sh[1][0] + sh[1][1] + sh[1][2] + sh[1][3];
    float t2 = sh[2][0] + sh[2][1] + sh[2][2] + sh[2][3];
    float i0 = 1.0f / (t0 + EPSV), i1 = 1.0f / (t1 + EPSV), i2 = 1.0f / (t2 + EPSV);

    float e0, e1, e2;
    {
        float f0 = a0x * i0, f1 = a0y * i0, f2 = a0z * i0, f3 = a0w * i0;
        e0 = f0 * logf(f0 + EPSV) + f1 * logf(f1 + EPSV)
           + f2 * logf(f2 + EPSV) + f3 * logf(f3 + EPSV);
    }
    {
        float f0 = a1x * i1, f1 = a1y * i1, f2 = a1z * i1, f3 = a1w * i1;
        e1 = f0 * logf(f0 + EPSV) + f1 * logf(f1 + EPSV)
           + f2 * logf(f2 + EPSV) + f3 * logf(f3 + EPSV);
    }
    {
        float f0 = a2x * i2, f1 = a2y * i2, f2 = a2z * i2, f3 = a2w * i2;
        e2 = f0 * logf(f0 + EPSV) + f1 * logf(f1 + EPSV)
           + f2 * logf(f2 + EPSV) + f3 * logf(f3 + EPSV);
    }
    #pragma unroll
    for (int o = 16; o; o >>= 1) {
        e0 += __shfl_down_sync(0xffffffffu, e0, o);
        e1 += __shfl_down_sync(0xffffffffu, e1, o);
        e2 += __shfl_down_sync(0xffffffffu, e2, o);
    }
    __syncthreads();
    if (lane == 0) { sh[0][w] = e0; sh[1][w] = e1; sh[2][w] = e2; }
    __syncthreads();
    if (tid == 0) {
        g_ent[0 * MM + r] = -(sh[0][0] + sh[0][1] + sh[0][2] + sh[0][3]);
        g_ent[1 * MM + r] = -(sh[1][0] + sh[1][1] + sh[1][2] + sh[1][3]);
        g_ent[2 * MM + r] = -(sh[2][0] + sh[2][1] + sh[2][2] + sh[2][3]);
    }

    store4h(v0, g_f, 0LL * MM * HH + off);
    store4h(v1, g_f, 1LL * MM * HH + off);
    store4h(v2, g_f, 2LL * MM * HH + off);
    float4 tq = make_float4(v0.x + v1.x + v2.x, v0.y + v1.y + v2.y,
                            v0.z + v1.z + v2.z, v0.w + v1.w + v2.w);
    store4h(tq, g_f, 3LL * MM * HH + off);
}

// ----------------------------------------------------------------------------
// Weight prep (merged: gate weights + Wc transpose)
// ----------------------------------------------------------------------------
__global__ void prep_weights(const float* __restrict__ gW, const float* __restrict__ Wc) {
    int idx = blockIdx.x * blockDim.x + threadIdx.x;
    if (idx < HH * HH) {
        float wa = gW[idx];
        float wb = gW[HH * HH + idx];
        float wc = gW[2 * HH * HH + idx];
        g_Aw[idx] = __float2half_rn(wa + wb - 0.5f * wc);
        g_Wh[idx] = __float2half_rn(0.5f * wc);
    }
    if (idx < HH) g_wlast[idx] = gW[3 * HH * HH + idx];
    if (idx < HH * CC) {
        int k = idx / CC, c = idx % CC;
        g_WcT[c * HH + k] = Wc[k * CC + c];
    }
}

// All three GNN weight conversions in one launch
#define N4_W0 (H3 * HH / 4)
#define N4_W1 (HH * HH / 4)
__global__ void conv_w_all(const float* __restrict__ W0, const float* __restrict__ W1,
                           const float* __restrict__ W2) {
    int i = blockIdx.x * blockDim.x + threadIdx.x;
    if (i < N4_W0) {
        float4 v = ((const float4*)W0)[i];
        store4h(v, g_W0, (long long)i * 4);
    } else if (i < N4_W0 + N4_W1) {
        int j = i - N4_W0;
        float4 v = ((const float4*)W1)[j];
        store4h(v, g_W1, (long long)j * 4);
    } else if (i < N4_W0 + 2 * N4_W1) {
        int j = i - N4_W0 - N4_W1;
        float4 v = ((const float4*)W2)[j];
        store4h(v, g_W2, (long long)j * 4);
    }
}

// ----------------------------------------------------------------------------
// gate_fuse (half): rows [rbase, rbase+MHALF)
// ----------------------------------------------------------------------------
__global__ void gate_fuse_kernel(const float* __restrict__ gate_b, int rbase) {
    long long r = rbase + blockIdx.x;
    int m = blockIdx.y;
    float e = g_ent[(long long)m * MM + r];
    int j = threadIdx.x * 4;
    long long gi = ((long long)m * MM + r) * HH + j;
    long long ti = (3LL * MM + r) * HH + j;
    float2 gv0 = __half22float2(*(const __half2*)(g_G + gi));
    float2 gv1 = __half22float2(*(const __half2*)(g_G + gi + 2));
    float2 tv0 = __half22float2(*(const __half2*)(g_G + ti));
    float2 tv1 = __half22float2(*(const __half2*)(g_G + ti + 2));
    float2 fv0 = __half22float2(*(const __half2*)(g_f + gi));
    float2 fv1 = __half22float2(*(const __half2*)(g_f + gi + 2));
    float4 wv = *(const float4*)(g_wlast + j);
    float4 bv = *(const float4*)(gate_b + j);

    float zx = gv0.x + tv0.x + e * wv.x + bv.x;
    float zy = gv0.y + tv0.y + e * wv.y + bv.y;
    float zz = gv1.x + tv1.x + e * wv.z + bv.z;
    float zw = gv1.y + tv1.y + e * wv.w + bv.w;
    float4 o;
    o.x = fv0.x / (1.0f + expf(-zx));
    o.y = fv0.y / (1.0f + expf(-zy));
    o.z = fv1.x / (1.0f + expf(-zz));
    o.w = fv1.y / (1.0f + expf(-zw));
    store4h(o, g_h0, r * H3 + m * HH + j);
}

// ----------------------------------------------------------------------------
// Degree: dsi + cache fp16(sp+tp)
// ----------------------------------------------------------------------------
__global__ void degree_kernel(const float* __restrict__ sp, const float* __restrict__ tp) {
    __shared__ float sh[8];
    long long b = blockIdx.y, i = blockIdx.x;
    long long base = (b * SS + i) * SS;
    const float4* rs = (const float4*)(sp + base);
    const float4* rt = (const float4*)(tp + base);
    float4 a = rs[threadIdx.x], c = rt[threadIdx.x];
    float4 sm4 = make_float4(a.x + c.x, a.y + c.y, a.z + c.z, a.w + c.w);
    store4h(sm4, g_sumh, base + threadIdx.x * 4);
    float s = sm4.x + sm4.y + sm4.z + sm4.w;
    #pragma unroll
    for (int o = 16; o; o >>= 1) s += __shfl_down_sync(0xffffffffu, s, o);
    int lane = threadIdx.x & 31, w = threadIdx.x >> 5;
    if (lane == 0) sh[w] = s;
    __syncthreads();
    if (threadIdx.x == 0) {
        float D = 1.0f + 0.5f * (sh[0] + sh[1] + sh[2] + sh[3] + sh[4] + sh[5] + sh[6] + sh[7]);
        g_dsi[b * SS + i] = 1.0f / sqrtf(D + EPSV);
    }
}

__global__ void normadj_kernel() {
    long long n4 = (long long)BB * SS * SS / 4;
    for (long long g = (long long)blockIdx.x * blockDim.x + threadIdx.x; g < n4;
         g += (long long)gridDim.x * blockDim.x) {
        long long e = g * 4;
        int b = (int)(e / ((long long)SS * SS));
        long long rrem = e % ((long long)SS * SS);
        int i = (int)(rrem / SS);
        int j = (int)(rrem % SS);
        float2 s0 = __half22float2(*(const __half2*)(g_sumh + e));
        float2 s1 = __half22float2(*(const __half2*)(g_sumh + e + 2));
        float di = g_dsi[(long long)b * SS + i];
        const float* dj = g_dsi + (long long)b * SS + j;
        float4 o;
        o.x = (0.5f * s0.x + (j + 0 == i ? 1.0f : 0.0f)) * di * dj[0];
        o.y = (0.5f * s0.y + (j + 1 == i ? 1.0f : 0.0f)) * di * dj[1];
        o.z = (0.5f * s1.x + (j + 2 == i ? 1.0f : 0.0f)) * di * dj[2];
        o.w = (0.5f * s1.y + (j + 3 == i ? 1.0f : 0.0f)) * di * dj[3];
        store4h(o, g_adj, e);
    }
}

// ----------------------------------------------------------------------------
// Classifier (half): rows [rbase, rbase+MHALF)
// ----------------------------------------------------------------------------
__global__ void classifier_kernel(const float* __restrict__ bc, float* __restrict__ out,
                                  int rbase) {
    __shared__ float sh[HH];
    long long r = rbase + blockIdx.x;
    for (int k = threadIdx.x; k < HH; k += 224)
        sh[k] = __half2float(g_h[r * HH + k]);
    __syncthreads();
    int w = threadIdx.x >> 5, lane = threadIdx.x & 31;
    if (w < CC) {
        const float* wrow = g_WcT + w * HH;
        float s = 0.0f;
        #pragma unroll
        for (int k = lane; k < HH; k += 32) s += sh[k] * wrow[k];
        #pragma unroll
        for (int o = 16; o; o >>= 1) s += __shfl_down_sync(0xffffffffu, s, o);
        if (lane == 0) out[r * CC + w] = s + bc[w];
    }
}

// ----------------------------------------------------------------------------
// Launch — SYMMETRIC half-pipelines: main = half-A, s2 = half-B (mirror),
// s3 = all shared prep (weights -> ePW, adjacency+conv -> eJoin).
// ----------------------------------------------------------------------------
extern "C" void kernel_launch(void* const* d_in, const int* in_sizes, int n_in,
                              void* d_out, int out_size) {
    const float* text   = (const float*)d_in[0];
    const float* audio  = (const float*)d_in[1];
    const float* visual = (const float*)d_in[2];
    const float* sp     = (const float*)d_in[3];
    const float* tp     = (const float*)d_in[4];
    const float* gate_W = (const float*)d_in[6];
    const float* gate_b = (const float*)d_in[7];
    const float* W0 = (const float*)d_in[8];
    const float* b0 = (const float*)d_in[9];
    const float* W1 = (const float*)d_in[10];
    const float* b1 = (const float*)d_in[11];
    const float* W2 = (const float*)d_in[12];
    const float* b2 = (const float*)d_in[13];
    const float* Wc = (const float*)d_in[14];
    const float* bc = (const float*)d_in[15];
    float* out = (float*)d_out;

    static bool init_done = false;
    static cudaStream_t s2, s3;
    static cudaEvent_t eFork, ePW, eJoin, eB;
    if (!init_done) {
        cudaFuncSetAttribute(mma_gemm<0, 0>, cudaFuncAttributeMaxDynamicSharedMemorySize, SMEM_BYTES);
        cudaFuncSetAttribute(mma_gemm<1, 0>, cudaFuncAttributeMaxDynamicSharedMemorySize, SMEM_BYTES);
        cudaFuncSetAttribute(mma_gemm<0, 1>, cudaFuncAttributeMaxDynamicSharedMemorySize, SMEM_BYTES);
        cudaStreamCreateWithFlags(&s2, cudaStreamNonBlocking);
        cudaStreamCreateWithFlags(&s3, cudaStreamNonBlocking);
        cudaEventCreateWithFlags(&eFork, cudaEventDisableTiming);
        cudaEventCreateWithFlags(&ePW, cudaEventDisableTiming);
        cudaEventCreateWithFlags(&eJoin, cudaEventDisableTiming);
        cudaEventCreateWithFlags(&eB, cudaEventDisableTiming);
        init_done = true;
    }

    #define SYM(p, s) cudaGetSymbolAddress((void**)&p, s)
    __half *f, *G, *h0, *adj, *tmp, *h;
    __half *Aw, *Wh, *W0p, *W1p, *W2p;
    SYM(f, g_f); SYM(G, g_G);
    SYM(h0, g_h0); SYM(adj, g_adj);
    SYM(tmp, g_tmp); SYM(h, g_h);
    SYM(Aw, g_Aw); SYM(Wh, g_Wh);
    SYM(W0p, g_W0); SYM(W1p, g_W1); SYM(W2p, g_W2);
    #undef SYM

    long long sF = (long long)MM * HH;
    dim3 gateh_grid(HH / BN, MHALF / BM, 4);       // (4, 64, 4) per half
    dim3 half_grid(HH / BN, MHALF / BM, 1);        // (4, 64, 1)
    dim3 adjh_grid(HH / BN, SS / BM, BB / 2);      // (4, 8, 8)
    long long sAdj = (long long)SS * SS, sL = (long long)SS * HH;

    // half-B pointer offsets (rows/batches 8192.. / 8..15)
    const long long hRow  = (long long)MHALF * HH;    // feats/G/tmp/h rows
    const long long hOffF = (long long)MHALF * H3;    // h0 rows
    const long long hOffA = 8LL * sAdj;               // adj batches

    // fork
    cudaEventRecord(eFork, 0);
    cudaStreamWaitEvent(s2, eFork, 0);
    cudaStreamWaitEvent(s3, eFork, 0);

    // s3: shared prep — gate weights first (unblocks both gates), then adjacency
    prep_weights<<<(HH * HH + 255) / 256, 256, 0, s3>>>(gate_W, Wc);
    cudaEventRecord(ePW, s3);
    degree_kernel<<<dim3(SS, BB), 256, 0, s3>>>(sp, tp);
    normadj_kernel<<<8192, 256, 0, s3>>>();
    conv_w_all<<<(N4_W0 + 2 * N4_W1 + 255) / 256, 256, 0, s3>>>(W0, W1, W2);
    cudaEventRecord(eJoin, s3);

    // main: half-A pipeline
    prep_feats<<<MHALF, 128>>>(text, audio, visual, 0);
    cudaStreamWaitEvent(0, ePW, 0);
    mma_gemm<0, 1><<<gateh_grid, 256, SMEM_BYTES>>>(f, Aw, Wh, nullptr, G,
                                                    MHALF, HH, HH, sF, 0, sF);
    gate_fuse_kernel<<<dim3(MHALF, 3), 128>>>(gate_b, 0);
    cudaStreamWaitEvent(0, eJoin, 0);

    // s2: half-B pipeline (mirror of main)
    prep_feats<<<MHALF, 128, 0, s2>>>(text, audio, visual, MHALF);
    cudaStreamWaitEvent(s2, ePW, 0);
    mma_gemm<0, 1><<<gateh_grid, 256, SMEM_BYTES, s2>>>(f + hRow, Aw, Wh, nullptr, G + hRow,
                                                        MHALF, HH, HH, sF, 0, sF);
    gate_fuse_kernel<<<dim3(MHALF, 3), 128, 0, s2>>>(gate_b, MHALF);
    cudaStreamWaitEvent(s2, eJoin, 0);

    // Layer 0
    mma_gemm<0, 0><<<half_grid, 256, SMEM_BYTES>>>(h0, W0p, nullptr, nullptr, tmp,
                                                   MHALF, HH, H3, 0, 0, 0);
    mma_gemm<0, 0><<<half_grid, 256, SMEM_BYTES, s2>>>(h0 + hOffF, W0p, nullptr, nullptr,
                                                       tmp + hRow, MHALF, HH, H3, 0, 0, 0);
    mma_gemm<1, 0><<<adjh_grid, 256, SMEM_BYTES>>>(adj, tmp, nullptr, b0, h,
                                                   SS, HH, SS, sAdj, sL, sL);
    mma_gemm<1, 0><<<adjh_grid, 256, SMEM_BYTES, s2>>>(adj + hOffA, tmp + hRow, nullptr, b0,
                                                       h + hRow, SS, HH, SS, sAdj, sL, sL);
    // Layer 1
    mma_gemm<0, 0><<<half_grid, 256, SMEM_BYTES>>>(h, W1p, nullptr, nullptr, tmp,
                                                   MHALF, HH, HH, 0, 0, 0);
    mma_gemm<0, 0><<<half_grid, 256, SMEM_BYTES, s2>>>(h + hRow, W1p, nullptr, nullptr,
                                                       tmp + hRow, MHALF, HH, HH, 0, 0, 0);
    mma_gemm<1, 0><<<adjh_grid, 256, SMEM_BYTES>>>(adj, tmp, nullptr, b1, h,
                                                   SS, HH, SS, sAdj, sL, sL);
    mma_gemm<1, 0><<<adjh_grid, 256, SMEM_BYTES, s2>>>(adj + hOffA, tmp + hRow, nullptr, b1,
                                                       h + hRow, SS, HH, SS, sAdj, sL, sL);
    // Layer 2
    mma_gemm<0, 0><<<half_grid, 256, SMEM_BYTES>>>(h, W2p, nullptr, nullptr, tmp,
                                                   MHALF, HH, HH, 0, 0, 0);
    mma_gemm<0, 0><<<half_grid, 256, SMEM_BYTES, s2>>>(h + hRow, W2p, nullptr, nullptr,
                                                       tmp + hRow, MHALF, HH, HH, 0, 0, 0);
    mma_gemm<1, 0><<<adjh_grid, 256, SMEM_BYTES>>>(adj, tmp, nullptr, b2, h,
                                                   SS, HH, SS, sAdj, sL, sL);
    mma_gemm<1, 0><<<adjh_grid, 256, SMEM_BYTES, s2>>>(adj + hOffA, tmp + hRow, nullptr, b2,
                                                       h + hRow, SS, HH, SS, sAdj, sL, sL);

    // classifier per half, join at end
    classifier_kernel<<<MHALF, 224>>>(bc, out, 0);
    classifier_kernel<<<MHALF, 224, 0, s2>>>(bc, out, MHALF);
    cudaEventRecord(eB, s2);
    cudaStreamWaitEvent(0, eB, 0);
}